// round 1
// baseline (speedup 1.0000x reference)
#include <cuda_runtime.h>
#include <math.h>

// ---------------------------------------------------------------------------
// Problem constants (fixed shapes from reference)
// ---------------------------------------------------------------------------
#define KB_ 4
#define KT_ 4096
#define KDIM_ 64
#define KHID_ 256
#define KROWS_ (KB_ * KT_)   // 16384

// Scratch (device globals; no allocation allowed)
__device__ float g_h[KROWS_ * KHID_];        // hidden / residual stream
__device__ float g_ln[KROWS_ * KHID_];       // layernorm output
__device__ float g_qkv[KROWS_ * 3 * KHID_];  // qkv projections
__device__ float g_m1[KROWS_ * KHID_];       // mlp intermediate

// ---------------------------------------------------------------------------
// Generic tiled SGEMM: out[M,N] = A[M,K] @ W[K,N] + bias (+gelu | +residual)
// BM=128, BK=8, 256 threads, per-thread TM x TN microtile.
// EPI: 0 = bias, 1 = bias+gelu(exact), 2 = bias+residual
// ---------------------------------------------------------------------------
template <int BN, int TN, int EPI>
__global__ __launch_bounds__(256)
void gemm_k(const float* __restrict__ A, const float* __restrict__ W,
            const float* __restrict__ bias, const float* __restrict__ res,
            float* __restrict__ out, int M, int K, int N)
{
    constexpr int BM = 128, BK = 8, TM = 8;
    __shared__ float As[BK][BM + 4];  // +4 pad: conflict-free transposed stores
    __shared__ float Bs[BK][BN];

    const int tid = threadIdx.x;
    const int tx = tid & 15;          // N direction (16)
    const int ty = tid >> 4;          // M direction (16)
    const int m0 = blockIdx.y * BM;
    const int n0 = blockIdx.x * BN;

    float acc[TM][TN];
#pragma unroll
    for (int i = 0; i < TM; i++)
#pragma unroll
        for (int j = 0; j < TN; j++) acc[i][j] = 0.f;

    const int arow = tid >> 1;            // 128 rows, 2 float4 per row
    const int ak = (tid & 1) * 4;
    const int brow = tid / (BN / 4);
    const int bcol = (tid % (BN / 4)) * 4;

    for (int kt = 0; kt < K; kt += BK) {
        float4 av = *(const float4*)&A[(size_t)(m0 + arow) * K + kt + ak];
        As[ak + 0][arow] = av.x;
        As[ak + 1][arow] = av.y;
        As[ak + 2][arow] = av.z;
        As[ak + 3][arow] = av.w;
        if (BN == 128 || tid < BK * BN / 4) {
            *(float4*)&Bs[brow][bcol] =
                *(const float4*)&W[(size_t)(kt + brow) * N + n0 + bcol];
        }
        __syncthreads();
#pragma unroll
        for (int kk = 0; kk < BK; kk++) {
            float af[TM], bf[TN];
#pragma unroll
            for (int i = 0; i < TM; i += 4)
                *(float4*)&af[i] = *(const float4*)&As[kk][ty * TM + i];
#pragma unroll
            for (int j = 0; j < TN; j += 4)
                *(float4*)&bf[j] = *(const float4*)&Bs[kk][tx * TN + j];
#pragma unroll
            for (int i = 0; i < TM; i++)
#pragma unroll
                for (int j = 0; j < TN; j++)
                    acc[i][j] = fmaf(af[i], bf[j], acc[i][j]);
        }
        __syncthreads();
    }

#pragma unroll
    for (int i = 0; i < TM; i++) {
        const int m = m0 + ty * TM + i;
        float vals[TN];
#pragma unroll
        for (int j = 0; j < TN; j++) {
            const int n = n0 + tx * TN + j;
            float v = acc[i][j] + bias[n];
            if (EPI == 1) v = 0.5f * v * (1.f + erff(v * 0.70710678118654752f));
            if (EPI == 2) v += res[(size_t)m * N + n];
            vals[j] = v;
        }
#pragma unroll
        for (int j = 0; j < TN; j += 4)
            *(float4*)&out[(size_t)m * N + n0 + tx * TN + j] = *(float4*)&vals[j];
    }
}

// ---------------------------------------------------------------------------
// LayerNorm: one warp per 256-wide row
// ---------------------------------------------------------------------------
__global__ __launch_bounds__(256)
void ln_k(const float* __restrict__ x, const float* __restrict__ g,
          const float* __restrict__ b, float* __restrict__ y)
{
    const int wid = threadIdx.x >> 5;
    const int lane = threadIdx.x & 31;
    const int row = blockIdx.x * 8 + wid;
    const float* xr = x + (size_t)row * KHID_;

    float v[8];
    float s = 0.f, s2 = 0.f;
#pragma unroll
    for (int i = 0; i < 8; i++) {
        v[i] = xr[lane + 32 * i];
        s += v[i];
        s2 += v[i] * v[i];
    }
#pragma unroll
    for (int o = 16; o; o >>= 1) {
        s += __shfl_xor_sync(0xffffffffu, s, o);
        s2 += __shfl_xor_sync(0xffffffffu, s2, o);
    }
    const float mu = s * (1.f / 256.f);
    const float var = s2 * (1.f / 256.f) - mu * mu;
    const float r = rsqrtf(var + 1e-5f);
    float* yr = y + (size_t)row * KHID_;
#pragma unroll
    for (int i = 0; i < 8; i++) {
        const int d = lane + 32 * i;
        yr[d] = (v[i] - mu) * r * g[d] + b[d];
    }
}

// ---------------------------------------------------------------------------
// Windowed attention (HISTORY=128, self-inclusive -> <=129 keys).
// Block: 64 queries of one batch. Key range [t0-128, t0+63] = up to three
// 64-aligned key tiles. Exact (non-online) softmax: full S tile in smem.
// Residual fused: h[row] += attn_out[row].
// qkv layout per row: [q(256) | k(256) | v(256)]
// ---------------------------------------------------------------------------
struct AttnSmem {
    float QsT[256][65];   // Q transposed [d][m], pitch 65 (conflict-free)
    float KVs[256][65];   // K transposed [d][n]; reused as V [64][260] (same size)
    float S[64][196];     // scores / probabilities, up to 192 key columns
    float rinv[64];       // 1/rowsum
};

__global__ __launch_bounds__(256)
void attn_k(const float* __restrict__ qkv, float* __restrict__ h)
{
    extern __shared__ char sm_raw[];
    AttnSmem& sm = *reinterpret_cast<AttnSmem*>(sm_raw);

    const int tid = threadIdx.x;
    const int tx = tid & 15;   // key / dim direction
    const int ty = tid >> 4;   // query direction
    const int b = blockIdx.x >> 6;    // 64 query tiles per batch
    const int qt = blockIdx.x & 63;
    const int t0 = qt * 64;
    const int g0 = b * KT_ + t0;
    const float scale = 1.f / 16.f;   // 1/sqrt(256)

    // Load Q (scaled) transposed: thread = one dim column, loop rows
    for (int i = 0; i < 64; i++)
        sm.QsT[tid][i] = qkv[(size_t)(g0 + i) * 768 + tid] * scale;

    const int kstart = (t0 - 128 > 0) ? (t0 - 128) : 0;
    const int nk = t0 + 64 - kstart;       // 64 / 128 / 192
    const int ntiles = nk >> 6;

    // ---- S = Q K^T (3 key tiles max), masked ----
    for (int kt = 0; kt < ntiles; kt++) {
        const int kb = kstart + kt * 64;
        const int kg0 = b * KT_ + kb;
        __syncthreads();  // protect KVs from previous iteration's readers (and Q load)
        for (int i = 0; i < 64; i++)
            sm.KVs[tid][i] = qkv[(size_t)(kg0 + i) * 768 + 256 + tid];
        __syncthreads();

        float acc[4][4] = {};
        for (int d = 0; d < 256; d++) {
            float qf[4], kf[4];
#pragma unroll
            for (int i = 0; i < 4; i++) qf[i] = sm.QsT[d][ty * 4 + i];
#pragma unroll
            for (int j = 0; j < 4; j++) kf[j] = sm.KVs[d][tx * 4 + j];
#pragma unroll
            for (int i = 0; i < 4; i++)
#pragma unroll
                for (int j = 0; j < 4; j++)
                    acc[i][j] = fmaf(qf[i], kf[j], acc[i][j]);
        }
#pragma unroll
        for (int i = 0; i < 4; i++) {
            const int q = t0 + ty * 4 + i;
#pragma unroll
            for (int j = 0; j < 4; j++) {
                const int k = kb + tx * 4 + j;
                const int dlt = q - k;
                sm.S[ty * 4 + i][kt * 64 + tx * 4 + j] =
                    (dlt >= 0 && dlt <= 128) ? acc[i][j] : -1e30f;
            }
        }
    }
    __syncthreads();

    // ---- softmax: one warp per row (8 warps x 8 rows) ----
    const int wid = tid >> 5, lane = tid & 31;
    for (int r = 0; r < 8; r++) {
        const int m = wid * 8 + r;
        float mx = -1e30f;
        for (int j = lane; j < nk; j += 32) mx = fmaxf(mx, sm.S[m][j]);
#pragma unroll
        for (int o = 16; o; o >>= 1) mx = fmaxf(mx, __shfl_xor_sync(0xffffffffu, mx, o));
        float ssum = 0.f;
        for (int j = lane; j < nk; j += 32) {
            const float e = __expf(sm.S[m][j] - mx);
            sm.S[m][j] = e;
            ssum += e;
        }
#pragma unroll
        for (int o = 16; o; o >>= 1) ssum += __shfl_xor_sync(0xffffffffu, ssum, o);
        if (lane == 0) sm.rinv[m] = 1.f / ssum;
    }
    __syncthreads();

    // ---- O = P V  (thread tile: 4 queries x 16 dims) ----
    float o[4][16] = {};
    float* Vs = &sm.KVs[0][0];  // reuse as V [64][260]
    for (int kt = 0; kt < ntiles; kt++) {
        const int kb = kstart + kt * 64;
        const int kg0 = b * KT_ + kb;
        __syncthreads();  // previous V tile fully consumed
        for (int i = 0; i < 64; i++)
            Vs[i * 260 + tid] = qkv[(size_t)(kg0 + i) * 768 + 512 + tid];
        __syncthreads();
        for (int jj = 0; jj < 64; jj++) {
            float p[4];
#pragma unroll
            for (int i = 0; i < 4; i++) p[i] = sm.S[ty * 4 + i][kt * 64 + jj];
            float vf[16];
#pragma unroll
            for (int j = 0; j < 16; j += 4)
                *(float4*)&vf[j] = *(const float4*)&Vs[jj * 260 + tx * 16 + j];
#pragma unroll
            for (int i = 0; i < 4; i++)
#pragma unroll
                for (int j = 0; j < 16; j++)
                    o[i][j] = fmaf(p[i], vf[j], o[i][j]);
        }
    }

    // ---- epilogue: h += O / rowsum (residual fused, in-place) ----
#pragma unroll
    for (int i = 0; i < 4; i++) {
        const int m = ty * 4 + i;
        const float rv = sm.rinv[m];
        const size_t base = (size_t)(g0 + m) * KHID_ + tx * 16;
#pragma unroll
        for (int j = 0; j < 16; j += 4) {
            float4 hv = *(const float4*)&h[base + j];
            float4 ov;
            ov.x = hv.x + o[i][j + 0] * rv;
            ov.y = hv.y + o[i][j + 1] * rv;
            ov.z = hv.z + o[i][j + 2] * rv;
            ov.w = hv.w + o[i][j + 3] * rv;
            *(float4*)&h[base + j] = ov;
        }
    }
}

// ---------------------------------------------------------------------------
// Launch
// ---------------------------------------------------------------------------
extern "C" void kernel_launch(void* const* d_in, const int* in_sizes, int n_in,
                              void* d_out, int out_size)
{
    (void)in_sizes; (void)n_in; (void)out_size;
    const float* x       = (const float*)d_in[0];
    const float* W_in    = (const float*)d_in[1];
    const float* b_in    = (const float*)d_in[2];
    const float* W_qkv   = (const float*)d_in[3];
    const float* b_qkv   = (const float*)d_in[4];
    const float* g_attn  = (const float*)d_in[5];
    const float* be_attn = (const float*)d_in[6];
    const float* g_mlp   = (const float*)d_in[7];
    const float* be_mlp  = (const float*)d_in[8];
    const float* W1      = (const float*)d_in[9];
    const float* b1      = (const float*)d_in[10];
    const float* W2      = (const float*)d_in[11];
    const float* b2      = (const float*)d_in[12];
    const float* W_out   = (const float*)d_in[13];
    const float* b_out   = (const float*)d_in[14];
    float* out = (float*)d_out;

    float *h_p, *ln_p, *qkv_p, *m1_p;
    cudaGetSymbolAddress((void**)&h_p, g_h);
    cudaGetSymbolAddress((void**)&ln_p, g_ln);
    cudaGetSymbolAddress((void**)&qkv_p, g_qkv);
    cudaGetSymbolAddress((void**)&m1_p, g_m1);

    cudaFuncSetAttribute((const void*)attn_k,
                         cudaFuncAttributeMaxDynamicSharedMemorySize,
                         (int)sizeof(AttnSmem));

    const dim3 blk(256);

    // 1) h = x @ W_in + b_in                 (16384 x 64 -> 256)
    gemm_k<128, 8, 0><<<dim3(KHID_ / 128, KROWS_ / 128), blk>>>(
        x, W_in, b_in, nullptr, h_p, KROWS_, KDIM_, KHID_);

    // 2) ln = LN(h; g_attn, be_attn)
    ln_k<<<KROWS_ / 8, blk>>>(h_p, g_attn, be_attn, ln_p);

    // 3) qkv = ln @ W_qkv + b_qkv            (K=256 -> N=768)
    gemm_k<128, 8, 0><<<dim3(3 * KHID_ / 128, KROWS_ / 128), blk>>>(
        ln_p, W_qkv, b_qkv, nullptr, qkv_p, KROWS_, KHID_, 3 * KHID_);

    // 4) h += window_attention(qkv)
    attn_k<<<KB_ * (KT_ / 64), blk, sizeof(AttnSmem)>>>(qkv_p, h_p);

    // 5) ln = LN(h; g_mlp, be_mlp)
    ln_k<<<KROWS_ / 8, blk>>>(h_p, g_mlp, be_mlp, ln_p);

    // 6) m1 = gelu(ln @ W1 + b1)
    gemm_k<128, 8, 1><<<dim3(KHID_ / 128, KROWS_ / 128), blk>>>(
        ln_p, W1, b1, nullptr, m1_p, KROWS_, KHID_, KHID_);

    // 7) h = h + (m1 @ W2 + b2)              (residual fused, in-place)
    gemm_k<128, 8, 2><<<dim3(KHID_ / 128, KROWS_ / 128), blk>>>(
        m1_p, W2, b2, h_p, h_p, KROWS_, KHID_, KHID_);

    // 8) out = h @ W_out + b_out             (N=64)
    gemm_k<64, 4, 0><<<dim3(KDIM_ / 64, KROWS_ / 128), blk>>>(
        h_p, W_out, b_out, nullptr, out, KROWS_, KHID_, KDIM_);
}

// round 2
// speedup vs baseline: 1.1747x; 1.1747x over previous
#include <cuda_runtime.h>
#include <math.h>

#define KB_ 4
#define KT_ 4096
#define KDIM_ 64
#define KHID_ 256
#define KROWS_ (KB_ * KT_)   // 16384
#define HIST_ 128

// Scratch (device globals; no allocation allowed)
__device__ float g_h[KROWS_ * KHID_];
__device__ float g_ln[KROWS_ * KHID_];
__device__ float g_qkv[KROWS_ * 3 * KHID_];
__device__ float g_m1[KROWS_ * KHID_];

// ---------------------------------------------------------------------------
// Packed fp32x2 helpers (FFMA2 — ptxas never auto-fuses; PTX-only)
// ---------------------------------------------------------------------------
__device__ __forceinline__ unsigned long long ffma2(unsigned long long a,
                                                    unsigned long long b,
                                                    unsigned long long c) {
    unsigned long long d;
    asm("fma.rn.f32x2 %0, %1, %2, %3;" : "=l"(d) : "l"(a), "l"(b), "l"(c));
    return d;
}
__device__ __forceinline__ unsigned long long pack2(float x, float y) {
    unsigned long long r;
    asm("mov.b64 %0, {%1, %2};" : "=l"(r) : "f"(x), "f"(y));
    return r;
}
__device__ __forceinline__ float2 unpack2(unsigned long long r) {
    float2 v;
    asm("mov.b64 {%0, %1}, %2;" : "=f"(v.x), "=f"(v.y) : "l"(r));
    return v;
}

// ---------------------------------------------------------------------------
// SGEMM with FFMA2: out[M,N] = A[M,K] @ W[K,N] + bias (+gelu | +residual)
// BM=128, BK=8, 256 threads. Thread tile: 8 m-rows x (NJ*2) n-cols,
// n = n0 + 32*j + 2*tx (+1). Accumulators packed along n (b64 pairs).
// A staged duplicated (a,a) pairs -> broadcast b64 loads, no packing in loop.
// EPI: 0 = bias, 1 = bias+gelu(exact), 2 = bias+residual
// ---------------------------------------------------------------------------
template <int BN, int EPI>
__global__ __launch_bounds__(256, 2)
void gemm_k(const float* __restrict__ A, const float* __restrict__ W,
            const float* __restrict__ bias, const float* __restrict__ res,
            float* __restrict__ out, int M, int K, int N)
{
    constexpr int BM = 128, BK = 8;
    constexpr int NJ = BN / 32;          // 4 for BN=128, 2 for BN=64
    constexpr int AP = 2 * BM + 8;       // As2 pitch (floats), 8B-aligned rows
    __shared__ float As2[BK * AP];       // duplicated-pair A, transposed [k][2m]
    __shared__ float Bs[BK][BN];

    const int tid = threadIdx.x;
    const int tx = tid & 15;
    const int ty = tid >> 4;
    const int m0 = blockIdx.y * BM;
    const int n0 = blockIdx.x * BN;

    unsigned long long acc2[8][NJ];
#pragma unroll
    for (int i = 0; i < 8; i++)
#pragma unroll
        for (int j = 0; j < NJ; j++) acc2[i][j] = 0ull;

    const int arow = tid >> 1;
    const int ak = (tid & 1) * 4;
    const int brow = tid / (BN / 4);
    const int bcol = (tid % (BN / 4)) * 4;

    for (int kt = 0; kt < K; kt += BK) {
        float4 av = *(const float4*)&A[(size_t)(m0 + arow) * K + kt + ak];
        {
            float tmp[4] = {av.x, av.y, av.z, av.w};
#pragma unroll
            for (int c = 0; c < 4; c++) {
                As2[(ak + c) * AP + 2 * arow]     = tmp[c];
                As2[(ak + c) * AP + 2 * arow + 1] = tmp[c];
            }
        }
        if (BN == 128 || tid < BK * BN / 4) {
            *(float4*)&Bs[brow][bcol] =
                *(const float4*)&W[(size_t)(kt + brow) * N + n0 + bcol];
        }
        __syncthreads();
#pragma unroll
        for (int kk = 0; kk < BK; kk++) {
            unsigned long long bf2[NJ];
#pragma unroll
            for (int j = 0; j < NJ; j++)
                bf2[j] = *(const unsigned long long*)&Bs[kk][j * 32 + 2 * tx];
#pragma unroll
            for (int i = 0; i < 8; i++) {
                unsigned long long af2 =
                    *(const unsigned long long*)&As2[kk * AP + 2 * (ty * 8 + i)];
#pragma unroll
                for (int j = 0; j < NJ; j++)
                    acc2[i][j] = ffma2(af2, bf2[j], acc2[i][j]);
            }
        }
        __syncthreads();
    }

#pragma unroll
    for (int i = 0; i < 8; i++) {
        const int m = m0 + ty * 8 + i;
#pragma unroll
        for (int j = 0; j < NJ; j++) {
            const int n = n0 + j * 32 + 2 * tx;
            float2 v = unpack2(acc2[i][j]);
            v.x += bias[n];
            v.y += bias[n + 1];
            if (EPI == 1) {
                v.x = 0.5f * v.x * (1.f + erff(v.x * 0.70710678118654752f));
                v.y = 0.5f * v.y * (1.f + erff(v.y * 0.70710678118654752f));
            }
            if (EPI == 2) {
                float2 r = *(const float2*)&res[(size_t)m * N + n];
                v.x += r.x; v.y += r.y;
            }
            *(float2*)&out[(size_t)m * N + n] = v;
        }
    }
}

// ---------------------------------------------------------------------------
// LayerNorm: one warp per 256-wide row
// ---------------------------------------------------------------------------
__global__ __launch_bounds__(256)
void ln_k(const float* __restrict__ x, const float* __restrict__ g,
          const float* __restrict__ b, float* __restrict__ y)
{
    const int wid = threadIdx.x >> 5;
    const int lane = threadIdx.x & 31;
    const int row = blockIdx.x * 8 + wid;
    const float* xr = x + (size_t)row * KHID_;

    float v[8];
    float s = 0.f, s2 = 0.f;
#pragma unroll
    for (int i = 0; i < 8; i++) {
        v[i] = xr[lane + 32 * i];
        s += v[i];
        s2 += v[i] * v[i];
    }
#pragma unroll
    for (int o = 16; o; o >>= 1) {
        s += __shfl_xor_sync(0xffffffffu, s, o);
        s2 += __shfl_xor_sync(0xffffffffu, s2, o);
    }
    const float mu = s * (1.f / 256.f);
    const float var = s2 * (1.f / 256.f) - mu * mu;
    const float r = rsqrtf(var + 1e-5f);
    float* yr = y + (size_t)row * KHID_;
#pragma unroll
    for (int i = 0; i < 8; i++) {
        const int d = lane + 32 * i;
        yr[d] = (v[i] - mu) * r * g[d] + b[d];
    }
}

// ---------------------------------------------------------------------------
// Windowed attention, FFMA2, 100 KB smem -> 2 blocks/SM, single wave.
// Block: 64 queries. Warp ty owns 8 query rows; lane tx owns 2 keys/tile (QK)
// and 4 dims/half (PV). d processed in two halves of 128.
// Scores kept in registers (kt unrolled to constant 3 with predication);
// softmax via full-warp shfl; P (scaled probs) stored once to smem.
// smem: Qs[64][130] | Ks[64][130] ; P[64][196] overlaps them; Vs[64][132].
// ---------------------------------------------------------------------------
#define ATTN_SMEM_FLOATS (16640 + 8448)

__global__ __launch_bounds__(256, 2)
void attn_k(const float* __restrict__ qkv, float* __restrict__ h)
{
    extern __shared__ float sm[];
    float* Qs = sm;              // 8320 floats, pitch 130
    float* Ks = sm + 8320;       // 8320 floats, pitch 130
    float* P  = sm;              // 64*196 = 12544 floats (overlaps Qs+Ks)
    float* Vs = sm + 16640;      // 8448 floats, pitch 132

    const int tid = threadIdx.x;
    const int tx = tid & 31;
    const int ty = tid >> 5;               // warp id: 8 query rows each
    const int b  = blockIdx.x >> 6;
    const int qt = blockIdx.x & 63;
    const int t0 = qt * 64;
    const int g0 = b * KT_ + t0;
    const int kstart = (t0 >= HIST_) ? (t0 - HIST_) : 0;
    const int ntiles = (t0 + 64 - kstart) >> 6;    // 1, 2 or 3

    const int lc  = tid & 127;              // loader: dim within half
    const int lr0 = (tid >> 7) * 32;        // loader: row group
    const float scale = 0.0625f;            // 1/sqrt(256)

    float sreg[3][8][2];

    // ---------------- QK^T (per key tile, accumulated over d-halves) -------
#pragma unroll
    for (int kt = 0; kt < 3; kt++) {
        if (kt < ntiles) {
            const int kg0 = b * KT_ + kstart + kt * 64;
            unsigned long long acc2[8][2];
#pragma unroll
            for (int i = 0; i < 8; i++) { acc2[i][0] = 0ull; acc2[i][1] = 0ull; }

#pragma unroll
            for (int half = 0; half < 2; half++) {
                __syncthreads();
                for (int rr = 0; rr < 32; rr++) {
                    const int r = lr0 + rr;
                    Qs[r * 130 + lc] =
                        qkv[(size_t)(g0 + r) * 768 + half * 128 + lc] * scale;
                    Ks[r * 130 + lc] =
                        qkv[(size_t)(kg0 + r) * 768 + 256 + half * 128 + lc];
                }
                __syncthreads();
#pragma unroll 4
                for (int t = 0; t < 64; t++) {
                    unsigned long long kf0 =
                        *(const unsigned long long*)&Ks[(2 * tx + 0) * 130 + 2 * t];
                    unsigned long long kf1 =
                        *(const unsigned long long*)&Ks[(2 * tx + 1) * 130 + 2 * t];
#pragma unroll
                    for (int i = 0; i < 8; i++) {
                        unsigned long long qf =
                            *(const unsigned long long*)&Qs[(ty * 8 + i) * 130 + 2 * t];
                        acc2[i][0] = ffma2(qf, kf0, acc2[i][0]);
                        acc2[i][1] = ffma2(qf, kf1, acc2[i][1]);
                    }
                }
            }
            // finalize + mask into sreg
#pragma unroll
            for (int i = 0; i < 8; i++) {
#pragma unroll
                for (int j = 0; j < 2; j++) {
                    float2 v = unpack2(acc2[i][j]);
                    const float s = v.x + v.y;
                    const int q = t0 + ty * 8 + i;
                    const int k = kstart + kt * 64 + 2 * tx + j;
                    const int d = q - k;
                    sreg[kt][i][j] = (d >= 0 && d <= HIST_) ? s : -3.0e38f;
                }
            }
        }
    }
    __syncthreads();   // all QK smem reads done before P overwrites Qs/Ks

    // ---------------- softmax in registers (row = full warp) ---------------
#pragma unroll
    for (int i = 0; i < 8; i++) {
        float mx = -3.0e38f;
#pragma unroll
        for (int kt = 0; kt < 3; kt++)
            if (kt < ntiles) {
                mx = fmaxf(mx, sreg[kt][i][0]);
                mx = fmaxf(mx, sreg[kt][i][1]);
            }
#pragma unroll
        for (int o = 16; o; o >>= 1)
            mx = fmaxf(mx, __shfl_xor_sync(0xffffffffu, mx, o));
        float sum = 0.f;
#pragma unroll
        for (int kt = 0; kt < 3; kt++)
            if (kt < ntiles) {
                const float e0 = __expf(sreg[kt][i][0] - mx);
                const float e1 = __expf(sreg[kt][i][1] - mx);
                sreg[kt][i][0] = e0;
                sreg[kt][i][1] = e1;
                sum += e0 + e1;
            }
#pragma unroll
        for (int o = 16; o; o >>= 1)
            sum += __shfl_xor_sync(0xffffffffu, sum, o);
        const float rinv = 1.0f / sum;
#pragma unroll
        for (int kt = 0; kt < 3; kt++)
            if (kt < ntiles) {
                float2 pv;
                pv.x = sreg[kt][i][0] * rinv;
                pv.y = sreg[kt][i][1] * rinv;
                *(float2*)&P[(ty * 8 + i) * 196 + kt * 64 + 2 * tx] = pv;
            }
    }

    // ---------------- O = P V (per d-half), residual fused ------------------
#pragma unroll
    for (int half = 0; half < 2; half++) {
        unsigned long long o2[8][2];
#pragma unroll
        for (int i = 0; i < 8; i++) { o2[i][0] = 0ull; o2[i][1] = 0ull; }

        for (int kt = 0; kt < ntiles; kt++) {
            const int kg0 = b * KT_ + kstart + kt * 64;
            __syncthreads();
            for (int rr = 0; rr < 32; rr++) {
                const int r = lr0 + rr;
                Vs[r * 132 + lc] =
                    qkv[(size_t)(kg0 + r) * 768 + 512 + half * 128 + lc];
            }
            __syncthreads();
            const float* Prow = &P[(ty * 8) * 196 + kt * 64];
#pragma unroll 4
            for (int jj = 0; jj < 64; jj++) {
                ulonglong2 vv = *(const ulonglong2*)&Vs[jj * 132 + tx * 4];
#pragma unroll
                for (int i = 0; i < 8; i++) {
                    const float p = Prow[i * 196 + jj];
                    const unsigned long long p2 = pack2(p, p);
                    o2[i][0] = ffma2(p2, vv.x, o2[i][0]);
                    o2[i][1] = ffma2(p2, vv.y, o2[i][1]);
                }
            }
        }
#pragma unroll
        for (int i = 0; i < 8; i++) {
            const size_t base =
                (size_t)(g0 + ty * 8 + i) * KHID_ + half * 128 + tx * 4;
            float4 hv = *(const float4*)&h[base];
            float2 a0 = unpack2(o2[i][0]);
            float2 a1 = unpack2(o2[i][1]);
            hv.x += a0.x; hv.y += a0.y; hv.z += a1.x; hv.w += a1.y;
            *(float4*)&h[base] = hv;
        }
    }
}

// ---------------------------------------------------------------------------
// Launch
// ---------------------------------------------------------------------------
extern "C" void kernel_launch(void* const* d_in, const int* in_sizes, int n_in,
                              void* d_out, int out_size)
{
    (void)in_sizes; (void)n_in; (void)out_size;
    const float* x       = (const float*)d_in[0];
    const float* W_in    = (const float*)d_in[1];
    const float* b_in    = (const float*)d_in[2];
    const float* W_qkv   = (const float*)d_in[3];
    const float* b_qkv   = (const float*)d_in[4];
    const float* g_attn  = (const float*)d_in[5];
    const float* be_attn = (const float*)d_in[6];
    const float* g_mlp   = (const float*)d_in[7];
    const float* be_mlp  = (const float*)d_in[8];
    const float* W1      = (const float*)d_in[9];
    const float* b1      = (const float*)d_in[10];
    const float* W2      = (const float*)d_in[11];
    const float* b2      = (const float*)d_in[12];
    const float* W_out   = (const float*)d_in[13];
    const float* b_out   = (const float*)d_in[14];
    float* out = (float*)d_out;

    float *h_p, *ln_p, *qkv_p, *m1_p;
    cudaGetSymbolAddress((void**)&h_p, g_h);
    cudaGetSymbolAddress((void**)&ln_p, g_ln);
    cudaGetSymbolAddress((void**)&qkv_p, g_qkv);
    cudaGetSymbolAddress((void**)&m1_p, g_m1);

    const int attn_smem = ATTN_SMEM_FLOATS * 4;   // 100352 B
    cudaFuncSetAttribute((const void*)attn_k,
                         cudaFuncAttributeMaxDynamicSharedMemorySize, attn_smem);

    const dim3 blk(256);

    // 1) h = x @ W_in + b_in
    gemm_k<128, 0><<<dim3(KHID_ / 128, KROWS_ / 128), blk>>>(
        x, W_in, b_in, nullptr, h_p, KROWS_, KDIM_, KHID_);

    // 2) ln = LN(h; g_attn, be_attn)
    ln_k<<<KROWS_ / 8, blk>>>(h_p, g_attn, be_attn, ln_p);

    // 3) qkv = ln @ W_qkv + b_qkv
    gemm_k<128, 0><<<dim3(3 * KHID_ / 128, KROWS_ / 128), blk>>>(
        ln_p, W_qkv, b_qkv, nullptr, qkv_p, KROWS_, KHID_, 3 * KHID_);

    // 4) h += window_attention(qkv)
    attn_k<<<KB_ * (KT_ / 64), blk, attn_smem>>>(qkv_p, h_p);

    // 5) ln = LN(h; g_mlp, be_mlp)
    ln_k<<<KROWS_ / 8, blk>>>(h_p, g_mlp, be_mlp, ln_p);

    // 6) m1 = gelu(ln @ W1 + b1)
    gemm_k<128, 1><<<dim3(KHID_ / 128, KROWS_ / 128), blk>>>(
        ln_p, W1, b1, nullptr, m1_p, KROWS_, KHID_, KHID_);

    // 7) h = h + (m1 @ W2 + b2)
    gemm_k<128, 2><<<dim3(KHID_ / 128, KROWS_ / 128), blk>>>(
        m1_p, W2, b2, h_p, h_p, KROWS_, KHID_, KHID_);

    // 8) out = h @ W_out + b_out
    gemm_k<64, 0><<<dim3(KDIM_ / 64, KROWS_ / 128), blk>>>(
        h_p, W_out, b_out, nullptr, out, KROWS_, KHID_, KDIM_);
}